// round 14
// baseline (speedup 1.0000x reference)
#include <cuda_runtime.h>
#include <cstdint>

// Problem constants
#define B_    32
#define H_    14
#define W_    14
#define L_    196          // H*W
#define NPOS  6272         // B*L
#define CIN   1024
#define WIDTH 256
#define OUTC  1024
#define KC    16           // codewords per codebook
#define TILE_N 32          // positions per block
#define SAF   20           // attn row stride in floats (16B-aligned rows)

// ---------------- scratch ----------------
__device__ float g_out1[WIDTH * NPOS];   // channel-major [c][n]
__device__ float g_out2[WIDTH * NPOS];
__device__ float g_out3[OUTC  * NPOS];
__device__ float g_sc1[WIDTH], g_sh1[WIDTH];
__device__ float g_sc2[WIDTH], g_sh2[WIDTH];
__device__ float g_sc3[OUTC],  g_sh3[OUTC];

// GEMM core: 32x16x256 per codebook; attn as float4 rows (stride SAF).
// Per thread: 512 FFMA + 48 LDS (was 144).
__device__ __forceinline__ void gemm_cb(const float* attn_s, const float* lut_s,
                                        int pn, int po, float acc[8][4]) {
#pragma unroll
    for (int kb = 0; kb < 4; ++kb) {
        const float4 bv0 = ((const float4*)lut_s)[(kb * 4 + 0) * 64 + po];
        const float4 bv1 = ((const float4*)lut_s)[(kb * 4 + 1) * 64 + po];
        const float4 bv2 = ((const float4*)lut_s)[(kb * 4 + 2) * 64 + po];
        const float4 bv3 = ((const float4*)lut_s)[(kb * 4 + 3) * 64 + po];
#pragma unroll
        for (int i = 0; i < 8; ++i) {
            const float4 a = *(const float4*)(attn_s + (pn * 8 + i) * SAF + kb * 4);
            acc[i][0] = fmaf(a.x, bv0.x, acc[i][0]);
            acc[i][1] = fmaf(a.x, bv0.y, acc[i][1]);
            acc[i][2] = fmaf(a.x, bv0.z, acc[i][2]);
            acc[i][3] = fmaf(a.x, bv0.w, acc[i][3]);
            acc[i][0] = fmaf(a.y, bv1.x, acc[i][0]);
            acc[i][1] = fmaf(a.y, bv1.y, acc[i][1]);
            acc[i][2] = fmaf(a.y, bv1.z, acc[i][2]);
            acc[i][3] = fmaf(a.y, bv1.w, acc[i][3]);
            acc[i][0] = fmaf(a.z, bv2.x, acc[i][0]);
            acc[i][1] = fmaf(a.z, bv2.y, acc[i][1]);
            acc[i][2] = fmaf(a.z, bv2.z, acc[i][2]);
            acc[i][3] = fmaf(a.z, bv2.w, acc[i][3]);
            acc[i][0] = fmaf(a.w, bv3.x, acc[i][0]);
            acc[i][1] = fmaf(a.w, bv3.y, acc[i][1]);
            acc[i][2] = fmaf(a.w, bv3.z, acc[i][2]);
            acc[i][3] = fmaf(a.w, bv3.w, acc[i][3]);
        }
    }
}

// ======================= AMM layer 1 (1x1, ncb=256, sub=4) =================
__global__ __launch_bounds__(256, 2) void amm1_kernel(
    const float* __restrict__ x, const float* __restrict__ cent,
    const float* __restrict__ lut, const float* __restrict__ invt_p)
{
    __shared__ float lut_s[KC * 256];       // 16 KB
    __shared__ float attn_s[TILE_N * SAF];  // padded rows, 2.5 KB
    __shared__ float xv_s[4 * TILE_N];

    const int t  = threadIdx.x;
    const int n0 = blockIdx.x * TILE_N;
    const float invt = __ldg(invt_p);

    const int po = t & 63;     // column group: cols po*4 .. po*4+3
    const int pn = t >> 6;     // position group: pos pn*8 .. pn*8+7
    float acc[8][4];
#pragma unroll
    for (int i = 0; i < 8; ++i)
#pragma unroll
        for (int q = 0; q < 4; ++q) acc[i][q] = 0.f;

    // xv loader mapping (threads 0..127)
    const int lj  = t >> 5;
    const int lnl = t & 31;
    const int ln  = n0 + lnl;
    const int lb  = ln / L_;
    const int ll  = ln - lb * L_;
    const float* xbase = x + (size_t)lb * CIN * L_ + ll;

    // scoring mapping: warp sw, 16-lane group grp, codeword kk
    const int sw   = t >> 5;
    const int lane = t & 31;
    const int grp  = lane >> 4;
    const int kk   = lane & 15;

    for (int c = 0; c < 256; ++c) {
        // prefetch LUT slice into registers (latency hidden behind scoring)
        float4 lr[4];
        const float4* lp = (const float4*)(lut + (size_t)c * KC * WIDTH);
#pragma unroll
        for (int i = 0; i < 4; ++i) lr[i] = __ldg(lp + t + i * 256);

        if (lj < 4)
            xv_s[lj * TILE_N + lnl] = __ldg(xbase + (c * 4 + lj) * L_);
        __syncthreads();

        // scoring + softmax (each 16-lane group handles one position per pass)
        {
            const float* cp = cent + (size_t)(c * KC + kk) * 4;
            const float c0 = __ldg(cp + 0), c1 = __ldg(cp + 1);
            const float c2 = __ldg(cp + 2), c3 = __ldg(cp + 3);
            const float nrm = c0 * c0 + c1 * c1 + c2 * c2 + c3 * c3;
#pragma unroll
            for (int pass = 0; pass < 2; ++pass) {
                const int nl = pass * 16 + sw * 2 + grp;
                float s = c0 * xv_s[0 * TILE_N + nl] + c1 * xv_s[1 * TILE_N + nl]
                        + c2 * xv_s[2 * TILE_N + nl] + c3 * xv_s[3 * TILE_N + nl];
                s = (2.f * s - nrm) * invt;
                float m = s;
#pragma unroll
                for (int d = 8; d; d >>= 1)
                    m = fmaxf(m, __shfl_xor_sync(0xffffffffu, m, d, 16));
                const float e = __expf(s - m);
                float sum = e;
#pragma unroll
                for (int d = 8; d; d >>= 1)
                    sum += __shfl_xor_sync(0xffffffffu, sum, d, 16);
                attn_s[nl * SAF + kk] = e / sum;
            }
        }
#pragma unroll
        for (int i = 0; i < 4; ++i) ((float4*)lut_s)[t + i * 256] = lr[i];
        __syncthreads();

        gemm_cb(attn_s, lut_s, pn, po, acc);
        __syncthreads();
    }

    // store channel-major
#pragma unroll
    for (int q = 0; q < 4; ++q) {
        const int o = po * 4 + q;
        float* dst = g_out1 + (size_t)o * NPOS + n0 + pn * 8;
#pragma unroll
        for (int i = 0; i < 8; ++i) dst[i] = acc[i][q];
    }
}

// ============ AMM layer 2 (3x3 patches, ncb=256, sub=9, bn1+relu fused) ====
__global__ __launch_bounds__(256, 2) void amm2_kernel(
    const float* __restrict__ cent, const float* __restrict__ lut,
    const float* __restrict__ invt_p)
{
    __shared__ float lut_s[KC * 256];
    __shared__ float attn_s[TILE_N * SAF];
    __shared__ float xv_s[9 * TILE_N];

    const int t  = threadIdx.x;
    const int n0 = blockIdx.x * TILE_N;
    const float invt = __ldg(invt_p);

    const int po = t & 63;
    const int pn = t >> 6;
    float acc[8][4];
#pragma unroll
    for (int i = 0; i < 8; ++i)
#pragma unroll
        for (int q = 0; q < 4; ++q) acc[i][q] = 0.f;

    // precompute patch-gather slots (288 entries over 256 threads -> 2 rounds)
    int posn[2]; bool vld[2];
#pragma unroll
    for (int r = 0; r < 2; ++r) {
        const int idx = t + r * 256;
        vld[r] = false; posn[r] = 0;
        if (idx < 9 * TILE_N) {
            const int s9 = idx >> 5, nl = idx & 31;
            const int n = n0 + nl;
            const int b = n / L_;
            const int l = n - b * L_;
            const int h = l / W_, w = l - (l / W_) * W_;
            const int hh = h + s9 / 3 - 1;
            const int ww = w + s9 % 3 - 1;
            if (hh >= 0 && hh < H_ && ww >= 0 && ww < W_) {
                vld[r]  = true;
                posn[r] = b * L_ + hh * W_ + ww;
            }
        }
    }

    const int sw = t >> 5, lane = t & 31, grp = lane >> 4, kk = lane & 15;

    for (int c = 0; c < 256; ++c) {
        float4 lr[4];
        const float4* lp = (const float4*)(lut + (size_t)c * KC * WIDTH);
#pragma unroll
        for (int i = 0; i < 4; ++i) lr[i] = __ldg(lp + t + i * 256);

        const float sc1 = g_sc1[c], sh1 = g_sh1[c];
#pragma unroll
        for (int r = 0; r < 2; ++r) {
            const int idx = t + r * 256;
            if (idx < 9 * TILE_N) {
                float v = 0.f;
                if (vld[r])
                    v = fmaxf(g_out1[(size_t)c * NPOS + posn[r]] * sc1 + sh1, 0.f);
                xv_s[idx] = v;
            }
        }
        __syncthreads();

        {
            const float* cp = cent + (size_t)(c * KC + kk) * 9;
            float cw[9]; float nrm = 0.f;
#pragma unroll
            for (int j = 0; j < 9; ++j) { cw[j] = __ldg(cp + j); nrm += cw[j] * cw[j]; }
#pragma unroll
            for (int pass = 0; pass < 2; ++pass) {
                const int nl = pass * 16 + sw * 2 + grp;
                float s = 0.f;
#pragma unroll
                for (int j = 0; j < 9; ++j) s += cw[j] * xv_s[j * TILE_N + nl];
                s = (2.f * s - nrm) * invt;
                float m = s;
#pragma unroll
                for (int d = 8; d; d >>= 1)
                    m = fmaxf(m, __shfl_xor_sync(0xffffffffu, m, d, 16));
                const float e = __expf(s - m);
                float sum = e;
#pragma unroll
                for (int d = 8; d; d >>= 1)
                    sum += __shfl_xor_sync(0xffffffffu, sum, d, 16);
                attn_s[nl * SAF + kk] = e / sum;
            }
        }
#pragma unroll
        for (int i = 0; i < 4; ++i) ((float4*)lut_s)[t + i * 256] = lr[i];
        __syncthreads();

        gemm_cb(attn_s, lut_s, pn, po, acc);
        __syncthreads();
    }

#pragma unroll
    for (int q = 0; q < 4; ++q) {
        const int o = po * 4 + q;
        float* dst = g_out2 + (size_t)o * NPOS + n0 + pn * 8;
#pragma unroll
        for (int i = 0; i < 8; ++i) dst[i] = acc[i][q];
    }
}

// ======= AMM layer 3 (1x1, ncb=64, sub=4, out=1024, bn2+relu fused) ========
// grid.y splits the 1024 output columns into 4 chunks of 256
__global__ __launch_bounds__(256, 2) void amm3_kernel(
    const float* __restrict__ cent, const float* __restrict__ lut,
    const float* __restrict__ invt_p)
{
    __shared__ float lut_s[KC * 256];
    __shared__ float attn_s[TILE_N * SAF];
    __shared__ float xv_s[4 * TILE_N];

    const int t  = threadIdx.x;
    const int n0 = blockIdx.x * TILE_N;
    const int obase = blockIdx.y << 8;
    const float invt = __ldg(invt_p);

    const int po = t & 63;
    const int pn = t >> 6;
    float acc[8][4];
#pragma unroll
    for (int i = 0; i < 8; ++i)
#pragma unroll
        for (int q = 0; q < 4; ++q) acc[i][q] = 0.f;

    const int lj  = t >> 5;
    const int lnl = t & 31;
    const int ln  = n0 + lnl;

    const int k0 = t >> 6;   // lut-row base for staging
    const int o4 = t & 63;   // float4 column within row

    const int sw = t >> 5, lane = t & 31, grp = lane >> 4, kk = lane & 15;

    for (int c = 0; c < 64; ++c) {
        float4 lr[4];
#pragma unroll
        for (int i = 0; i < 4; ++i)
            lr[i] = __ldg((const float4*)(lut + (size_t)(c * KC + k0 + i * 4) * OUTC + obase) + o4);

        if (lj < 4) {
            const int ch = c * 4 + lj;
            const float v = g_out2[(size_t)ch * NPOS + ln] * g_sc2[ch] + g_sh2[ch];
            xv_s[lj * TILE_N + lnl] = fmaxf(v, 0.f);
        }
        __syncthreads();

        {
            const float* cp = cent + (size_t)(c * KC + kk) * 4;
            const float c0 = __ldg(cp + 0), c1 = __ldg(cp + 1);
            const float c2 = __ldg(cp + 2), c3 = __ldg(cp + 3);
            const float nrm = c0 * c0 + c1 * c1 + c2 * c2 + c3 * c3;
#pragma unroll
            for (int pass = 0; pass < 2; ++pass) {
                const int nl = pass * 16 + sw * 2 + grp;
                float s = c0 * xv_s[0 * TILE_N + nl] + c1 * xv_s[1 * TILE_N + nl]
                        + c2 * xv_s[2 * TILE_N + nl] + c3 * xv_s[3 * TILE_N + nl];
                s = (2.f * s - nrm) * invt;
                float m = s;
#pragma unroll
                for (int d = 8; d; d >>= 1)
                    m = fmaxf(m, __shfl_xor_sync(0xffffffffu, m, d, 16));
                const float e = __expf(s - m);
                float sum = e;
#pragma unroll
                for (int d = 8; d; d >>= 1)
                    sum += __shfl_xor_sync(0xffffffffu, sum, d, 16);
                attn_s[nl * SAF + kk] = e / sum;
            }
        }
#pragma unroll
        for (int i = 0; i < 4; ++i) ((float4*)lut_s)[t + i * 256] = lr[i];
        __syncthreads();

        gemm_cb(attn_s, lut_s, pn, po, acc);
        __syncthreads();
    }

#pragma unroll
    for (int q = 0; q < 4; ++q) {
        const int o = obase + po * 4 + q;
        float* dst = g_out3 + (size_t)o * NPOS + n0 + pn * 8;
#pragma unroll
        for (int i = 0; i < 8; ++i) dst[i] = acc[i][q];
    }
}

// ================== BN batch-stats (one block per channel) =================
__global__ __launch_bounds__(256) void bn_stats_kernel(
    int which, const float* __restrict__ gw, const float* __restrict__ bw)
{
    const float* data; float* scale; float* shift;
    if (which == 0)      { data = g_out1; scale = g_sc1; shift = g_sh1; }
    else if (which == 1) { data = g_out2; scale = g_sc2; shift = g_sh2; }
    else                 { data = g_out3; scale = g_sc3; shift = g_sh3; }

    const int c = blockIdx.x, t = threadIdx.x;
    const float* p = data + (size_t)c * NPOS;
    float s = 0.f, s2 = 0.f;
    for (int i = t; i < NPOS; i += 256) {
        const float v = p[i];
        s += v; s2 += v * v;
    }
#pragma unroll
    for (int d = 16; d; d >>= 1) {
        s  += __shfl_xor_sync(0xffffffffu, s,  d);
        s2 += __shfl_xor_sync(0xffffffffu, s2, d);
    }
    __shared__ float sh_s[8], sh_s2[8];
    if ((t & 31) == 0) { sh_s[t >> 5] = s; sh_s2[t >> 5] = s2; }
    __syncthreads();
    if (t == 0) {
        s = 0.f; s2 = 0.f;
#pragma unroll
        for (int i = 0; i < 8; ++i) { s += sh_s[i]; s2 += sh_s2[i]; }
        const float m   = s  * (1.f / NPOS);
        const float var = s2 * (1.f / NPOS) - m * m;
        const float sc  = __ldg(gw + c) * rsqrtf(var + 1e-5f);
        scale[c] = sc;
        shift[c] = __ldg(bw + c) - m * sc;
    }
}

// ============== final: bn3 + residual + relu, channel-major out ============
__global__ __launch_bounds__(256) void final_kernel(
    const float* __restrict__ x, float* __restrict__ out)
{
    const int idx = blockIdx.x * 256 + threadIdx.x;
    if (idx >= B_ * OUTC * L_) return;
    const int l = idx % L_;
    const int c = (idx / L_) % OUTC;
    const int b = idx / (L_ * OUTC);
    const int n = b * L_ + l;
    const float v = g_out3[(size_t)c * NPOS + n] * g_sc3[c] + g_sh3[c] + x[idx];
    out[idx] = fmaxf(v, 0.f);
}

// === 1 dummy: shifts the ncu capture slot (I in {1,3}) onto amm1 or amm2 ===
__global__ void dummy_kernel() {}

// ==========================================================================
extern "C" void kernel_launch(void* const* d_in, const int* in_sizes, int n_in,
                              void* d_out, int out_size)
{
    (void)in_sizes; (void)n_in; (void)out_size;
    const float* x    = (const float*)d_in[0];
    const float* c1c  = (const float*)d_in[1];
    const float* c1l  = (const float*)d_in[2];
    const float* c1t  = (const float*)d_in[3];
    const float* c2c  = (const float*)d_in[4];
    const float* c2l  = (const float*)d_in[5];
    const float* c2t  = (const float*)d_in[6];
    const float* c3c  = (const float*)d_in[7];
    const float* c3l  = (const float*)d_in[8];
    const float* c3t  = (const float*)d_in[9];
    const float* bn1g = (const float*)d_in[10];
    const float* bn1b = (const float*)d_in[11];
    const float* bn2g = (const float*)d_in[12];
    const float* bn2b = (const float*)d_in[13];
    const float* bn3g = (const float*)d_in[14];
    const float* bn3b = (const float*)d_in[15];
    float* out = (float*)d_out;

    dummy_kernel<<<1, 32>>>();

    amm1_kernel<<<NPOS / TILE_N, 256>>>(x, c1c, c1l, c1t);
    bn_stats_kernel<<<WIDTH, 256>>>(0, bn1g, bn1b);

    amm2_kernel<<<NPOS / TILE_N, 256>>>(c2c, c2l, c2t);
    bn_stats_kernel<<<WIDTH, 256>>>(1, bn2g, bn2b);

    amm3_kernel<<<dim3(NPOS / TILE_N, 4), 256>>>(c3c, c3l, c3t);
    bn_stats_kernel<<<OUTC, 256>>>(2, bn3g, bn3b);
    final_kernel<<<(B_ * OUTC * L_ + 255) / 256, 256>>>(x, out);
}

// round 15
// speedup vs baseline: 1.1955x; 1.1955x over previous
#include <cuda_runtime.h>
#include <cstdint>

#define B_    32
#define H_    14
#define W_    14
#define L_    196
#define NPOS  6272
#define CIN   1024
#define WIDTH 256
#define OUTC  1024
#define KC    16
#define ROWS  24           // padded GEMM rows per block
#define SAF   17           // attn row stride (scalar broadcast loads)
#define NBLK  296          // 2 * 148
#define TB    21           // base tile; first 56 blocks get 22

// ---------------- scratch ----------------
__device__ float g_out1[WIDTH * NPOS];   // channel-major [c][n]
__device__ float g_out2[WIDTH * NPOS];
__device__ float g_out3[OUTC  * NPOS];
__device__ float g_sc1[WIDTH], g_sh1[WIDTH];
__device__ float g_sc2[WIDTH], g_sh2[WIDTH];
__device__ float g_sc3[OUTC],  g_sh3[OUTC];

// GEMM core: 24x16x256 per codebook; scalar broadcast attn (R3 style).
__device__ __forceinline__ void gemm_cb(const float* attn_s, const float* lut_s,
                                        int pn, int po, float acc[6][4]) {
#pragma unroll
    for (int k = 0; k < KC; ++k) {
        const float4 bv = ((const float4*)lut_s)[k * 64 + po];
#pragma unroll
        for (int i = 0; i < 6; ++i) {
            const float a = attn_s[(pn * 6 + i) * SAF + k];
            acc[i][0] = fmaf(a, bv.x, acc[i][0]);
            acc[i][1] = fmaf(a, bv.y, acc[i][1]);
            acc[i][2] = fmaf(a, bv.z, acc[i][2]);
            acc[i][3] = fmaf(a, bv.w, acc[i][3]);
        }
    }
}

__device__ __forceinline__ void epi_store(float* dst, int obase, int n0, int TILE,
                                          int pn, int po, const float acc[6][4]) {
#pragma unroll
    for (int i = 0; i < 6; ++i) {
        const int row = pn * 6 + i;
        if (row < TILE) {
            const int n = n0 + row;
#pragma unroll
            for (int q = 0; q < 4; ++q)
                dst[(size_t)(obase + po * 4 + q) * NPOS + n] = acc[i][q];
        }
    }
}

// ======================= AMM layer 1 (1x1, ncb=256, sub=4) =================
__global__ __launch_bounds__(256, 2) void amm1_kernel(
    const float* __restrict__ x, const float* __restrict__ cent,
    const float* __restrict__ lut, const float* __restrict__ invt_p)
{
    __shared__ float lut_s[KC * 256];       // 16 KB
    __shared__ float attn_s[ROWS * SAF];
    __shared__ float xv_s[4 * ROWS];

    const int t = threadIdx.x, bx = blockIdx.x;
    const int TILE = TB + (bx < 56);
    const int n0 = bx * TB + (bx < 56 ? bx : 56);
    const float invt = __ldg(invt_p);

    const int po = t & 63, pn = t >> 6;
    float acc[6][4];
#pragma unroll
    for (int i = 0; i < 6; ++i)
#pragma unroll
        for (int q = 0; q < 4; ++q) acc[i][q] = 0.f;

    // xv loader mapping: threads with (t&31)<24, t<128 stage xv_s[4][24]
    const int lj = t >> 5, lnl = t & 31;
    const bool ldr = (lj < 4) && (lnl < ROWS);
    const int lrow = min(lnl, TILE - 1);
    const int ln = n0 + lrow, lb = ln / L_, ll = ln - (ln / L_) * L_;
    const float* xbase = x + (size_t)lb * CIN * L_ + ll;

    // scoring mapping: 16 groups of 16 lanes; 2 passes cover 32 slots, use <24
    const int gg = t >> 4, kk = t & 15;

    for (int c = 0; c < 256; ++c) {
        float4 lr[4];
        const float4* lp = (const float4*)(lut + (size_t)c * KC * WIDTH);
#pragma unroll
        for (int i = 0; i < 4; ++i) lr[i] = __ldg(lp + t + i * 256);

        if (ldr)
            xv_s[lj * ROWS + lnl] = __ldg(xbase + (c * 4 + lj) * L_);
        __syncthreads();

        {
            const float* cp = cent + (size_t)(c * KC + kk) * 4;
            const float c0 = __ldg(cp + 0), c1 = __ldg(cp + 1);
            const float c2 = __ldg(cp + 2), c3 = __ldg(cp + 3);
            const float nrm = c0 * c0 + c1 * c1 + c2 * c2 + c3 * c3;
#pragma unroll
            for (int ps = 0; ps < 2; ++ps) {
                const int nl = ps * 16 + gg;     // uniform within 16-lane group
                if (nl < ROWS) {
                    float s = c0 * xv_s[0 * ROWS + nl] + c1 * xv_s[1 * ROWS + nl]
                            + c2 * xv_s[2 * ROWS + nl] + c3 * xv_s[3 * ROWS + nl];
                    s = (2.f * s - nrm) * invt;
                    float m = s;
#pragma unroll
                    for (int d = 8; d; d >>= 1)
                        m = fmaxf(m, __shfl_xor_sync(0xffffffffu, m, d, 16));
                    const float e = __expf(s - m);
                    float sum = e;
#pragma unroll
                    for (int d = 8; d; d >>= 1)
                        sum += __shfl_xor_sync(0xffffffffu, sum, d, 16);
                    attn_s[nl * SAF + kk] = e / sum;
                }
            }
        }
#pragma unroll
        for (int i = 0; i < 4; ++i) ((float4*)lut_s)[t + i * 256] = lr[i];
        __syncthreads();

        gemm_cb(attn_s, lut_s, pn, po, acc);
        __syncthreads();
    }
    epi_store(g_out1, 0, n0, TILE, pn, po, acc);
}

// ============ AMM layer 2 (3x3 patches, ncb=256, sub=9, bn1+relu fused) ====
__global__ __launch_bounds__(256, 2) void amm2_kernel(
    const float* __restrict__ cent, const float* __restrict__ lut,
    const float* __restrict__ invt_p)
{
    __shared__ float lut_s[KC * 256];
    __shared__ float attn_s[ROWS * SAF];
    __shared__ float xv_s[9 * ROWS];       // 216 entries

    const int t = threadIdx.x, bx = blockIdx.x;
    const int TILE = TB + (bx < 56);
    const int n0 = bx * TB + (bx < 56 ? bx : 56);
    const float invt = __ldg(invt_p);

    const int po = t & 63, pn = t >> 6;
    float acc[6][4];
#pragma unroll
    for (int i = 0; i < 6; ++i)
#pragma unroll
        for (int q = 0; q < 4; ++q) acc[i][q] = 0.f;

    // patch-gather precompute: thread t<216 owns xv_s slot t
    int posn = 0; bool vld = false;
    if (t < 9 * ROWS) {
        const int s9 = t / ROWS, nl = t - s9 * ROWS;
        const int n = n0 + min(nl, TILE - 1);
        const int b = n / L_, l = n - b * L_;
        const int h = l / W_, w = l - (l / W_) * W_;
        const int hh = h + s9 / 3 - 1, ww = w + s9 % 3 - 1;
        vld = (hh >= 0 && hh < H_ && ww >= 0 && ww < W_);
        posn = b * L_ + (vld ? hh * W_ + ww : 0);
    }

    const int gg = t >> 4, kk = t & 15;

    for (int c = 0; c < 256; ++c) {
        float4 lr[4];
        const float4* lp = (const float4*)(lut + (size_t)c * KC * WIDTH);
#pragma unroll
        for (int i = 0; i < 4; ++i) lr[i] = __ldg(lp + t + i * 256);

        if (t < 9 * ROWS) {
            const float sc1 = g_sc1[c], sh1 = g_sh1[c];
            float v = 0.f;
            if (vld)
                v = fmaxf(fmaf(__ldg(g_out1 + (size_t)c * NPOS + posn), sc1, sh1), 0.f);
            xv_s[t] = v;
        }
        __syncthreads();

        {
            const float* cp = cent + (size_t)(c * KC + kk) * 9;
            float cw[9]; float nrm = 0.f;
#pragma unroll
            for (int j = 0; j < 9; ++j) { cw[j] = __ldg(cp + j); nrm = fmaf(cw[j], cw[j], nrm); }
#pragma unroll
            for (int ps = 0; ps < 2; ++ps) {
                const int nl = ps * 16 + gg;
                if (nl < ROWS) {
                    float s = 0.f;
#pragma unroll
                    for (int j = 0; j < 9; ++j) s = fmaf(cw[j], xv_s[j * ROWS + nl], s);
                    s = (2.f * s - nrm) * invt;
                    float m = s;
#pragma unroll
                    for (int d = 8; d; d >>= 1)
                        m = fmaxf(m, __shfl_xor_sync(0xffffffffu, m, d, 16));
                    const float e = __expf(s - m);
                    float sum = e;
#pragma unroll
                    for (int d = 8; d; d >>= 1)
                        sum += __shfl_xor_sync(0xffffffffu, sum, d, 16);
                    attn_s[nl * SAF + kk] = e / sum;
                }
            }
        }
#pragma unroll
        for (int i = 0; i < 4; ++i) ((float4*)lut_s)[t + i * 256] = lr[i];
        __syncthreads();

        gemm_cb(attn_s, lut_s, pn, po, acc);
        __syncthreads();
    }
    epi_store(g_out2, 0, n0, TILE, pn, po, acc);
}

// ======= AMM layer 3 (1x1, ncb=64, sub=4, out=1024, bn2+relu fused) ========
// grid (296, 4): exactly 8 blocks per SM
__global__ __launch_bounds__(256, 2) void amm3_kernel(
    const float* __restrict__ cent, const float* __restrict__ lut,
    const float* __restrict__ invt_p)
{
    __shared__ float lut_s[KC * 256];
    __shared__ float attn_s[ROWS * SAF];
    __shared__ float xv_s[4 * ROWS];

    const int t = threadIdx.x, bx = blockIdx.x;
    const int obase = blockIdx.y << 8;
    const int TILE = TB + (bx < 56);
    const int n0 = bx * TB + (bx < 56 ? bx : 56);
    const float invt = __ldg(invt_p);

    const int po = t & 63, pn = t >> 6;
    float acc[6][4];
#pragma unroll
    for (int i = 0; i < 6; ++i)
#pragma unroll
        for (int q = 0; q < 4; ++q) acc[i][q] = 0.f;

    const int lj = t >> 5, lnl = t & 31;
    const bool ldr = (lj < 4) && (lnl < ROWS);
    const int ln = n0 + min(lnl, TILE - 1);

    const int k0 = t >> 6, o4 = t & 63;     // lut staging mapping
    const int gg = t >> 4, kk = t & 15;

    for (int c = 0; c < 64; ++c) {
        float4 lr[4];
#pragma unroll
        for (int i = 0; i < 4; ++i)
            lr[i] = __ldg((const float4*)(lut + (size_t)(c * KC + k0 + i * 4) * OUTC + obase) + o4);

        if (ldr) {
            const int ch = c * 4 + lj;
            const float v = fmaf(g_out2[(size_t)ch * NPOS + ln], g_sc2[ch], g_sh2[ch]);
            xv_s[lj * ROWS + lnl] = fmaxf(v, 0.f);
        }
        __syncthreads();

        {
            const float* cp = cent + (size_t)(c * KC + kk) * 4;
            const float c0 = __ldg(cp + 0), c1 = __ldg(cp + 1);
            const float c2 = __ldg(cp + 2), c3 = __ldg(cp + 3);
            const float nrm = c0 * c0 + c1 * c1 + c2 * c2 + c3 * c3;
#pragma unroll
            for (int ps = 0; ps < 2; ++ps) {
                const int nl = ps * 16 + gg;
                if (nl < ROWS) {
                    float s = c0 * xv_s[0 * ROWS + nl] + c1 * xv_s[1 * ROWS + nl]
                            + c2 * xv_s[2 * ROWS + nl] + c3 * xv_s[3 * ROWS + nl];
                    s = (2.f * s - nrm) * invt;
                    float m = s;
#pragma unroll
                    for (int d = 8; d; d >>= 1)
                        m = fmaxf(m, __shfl_xor_sync(0xffffffffu, m, d, 16));
                    const float e = __expf(s - m);
                    float sum = e;
#pragma unroll
                    for (int d = 8; d; d >>= 1)
                        sum += __shfl_xor_sync(0xffffffffu, sum, d, 16);
                    attn_s[nl * SAF + kk] = e / sum;
                }
            }
        }
#pragma unroll
        for (int i = 0; i < 4; ++i) ((float4*)lut_s)[t + i * 256] = lr[i];
        __syncthreads();

        gemm_cb(attn_s, lut_s, pn, po, acc);
        __syncthreads();
    }
    epi_store(g_out3, obase, n0, TILE, pn, po, acc);
}

// ================== BN batch-stats (one block per channel) =================
__global__ __launch_bounds__(256) void bn_stats_kernel(
    int which, const float* __restrict__ gw, const float* __restrict__ bw)
{
    const float* data; float* scale; float* shift;
    if (which == 0)      { data = g_out1; scale = g_sc1; shift = g_sh1; }
    else if (which == 1) { data = g_out2; scale = g_sc2; shift = g_sh2; }
    else                 { data = g_out3; scale = g_sc3; shift = g_sh3; }

    const int c = blockIdx.x, t = threadIdx.x;
    const float* p = data + (size_t)c * NPOS;
    float s = 0.f, s2 = 0.f;
    for (int i = t; i < NPOS; i += 256) {
        const float v = p[i];
        s += v; s2 += v * v;
    }
#pragma unroll
    for (int d = 16; d; d >>= 1) {
        s  += __shfl_xor_sync(0xffffffffu, s,  d);
        s2 += __shfl_xor_sync(0xffffffffu, s2, d);
    }
    __shared__ float sh_s[8], sh_s2[8];
    if ((t & 31) == 0) { sh_s[t >> 5] = s; sh_s2[t >> 5] = s2; }
    __syncthreads();
    if (t == 0) {
        s = 0.f; s2 = 0.f;
#pragma unroll
        for (int i = 0; i < 8; ++i) { s += sh_s[i]; s2 += sh_s2[i]; }
        const float m   = s  * (1.f / NPOS);
        const float var = s2 * (1.f / NPOS) - m * m;
        const float sc  = __ldg(gw + c) * rsqrtf(var + 1e-5f);
        scale[c] = sc;
        shift[c] = __ldg(bw + c) - m * sc;
    }
}

// ============== final: bn3 + residual + relu ===============================
__global__ __launch_bounds__(256) void final_kernel(
    const float* __restrict__ x, float* __restrict__ out)
{
    const int idx = blockIdx.x * 256 + threadIdx.x;
    if (idx >= B_ * OUTC * L_) return;
    const int l = idx % L_;
    const int c = (idx / L_) % OUTC;
    const int b = idx / (L_ * OUTC);
    const int n = b * L_ + l;
    const float v = g_out3[(size_t)c * NPOS + n] * g_sc3[c] + g_sh3[c] + x[idx];
    out[idx] = fmaxf(v, 0.f);
}

// === 1 dummy: shifts the ncu capture slot onto amm1 or amm2 ===
__global__ void dummy_kernel() {}

// ==========================================================================
extern "C" void kernel_launch(void* const* d_in, const int* in_sizes, int n_in,
                              void* d_out, int out_size)
{
    (void)in_sizes; (void)n_in; (void)out_size;
    const float* x    = (const float*)d_in[0];
    const float* c1c  = (const float*)d_in[1];
    const float* c1l  = (const float*)d_in[2];
    const float* c1t  = (const float*)d_in[3];
    const float* c2c  = (const float*)d_in[4];
    const float* c2l  = (const float*)d_in[5];
    const float* c2t  = (const float*)d_in[6];
    const float* c3c  = (const float*)d_in[7];
    const float* c3l  = (const float*)d_in[8];
    const float* c3t  = (const float*)d_in[9];
    const float* bn1g = (const float*)d_in[10];
    const float* bn1b = (const float*)d_in[11];
    const float* bn2g = (const float*)d_in[12];
    const float* bn2b = (const float*)d_in[13];
    const float* bn3g = (const float*)d_in[14];
    const float* bn3b = (const float*)d_in[15];
    float* out = (float*)d_out;

    dummy_kernel<<<1, 32>>>();

    amm1_kernel<<<NBLK, 256>>>(x, c1c, c1l, c1t);
    bn_stats_kernel<<<WIDTH, 256>>>(0, bn1g, bn1b);

    amm2_kernel<<<NBLK, 256>>>(c2c, c2l, c2t);
    bn_stats_kernel<<<WIDTH, 256>>>(1, bn2g, bn2b);

    amm3_kernel<<<dim3(NBLK, 4), 256>>>(c3c, c3l, c3t);
    bn_stats_kernel<<<OUTC, 256>>>(2, bn3g, bn3b);
    final_kernel<<<(B_ * OUTC * L_ + 255) / 256, 256>>>(x, out);
}

// round 17
// speedup vs baseline: 1.1992x; 1.0031x over previous
#include <cuda_runtime.h>
#include <cstdint>

#define B_    32
#define H_    14
#define W_    14
#define L_    196
#define NPOS  6272
#define CIN   1024
#define WIDTH 256
#define OUTC  1024
#define KC    16
#define ROWS  24           // padded GEMM rows per block
#define NBLK  296          // 2 * 148
#define TB    21           // base tile; first 56 blocks get 22

// ---------------- scratch ----------------
__device__ float g_out1[WIDTH * NPOS];   // channel-major [c][n]
__device__ float g_out2[WIDTH * NPOS];
__device__ float g_out3[OUTC  * NPOS];
__device__ float g_sc1[WIDTH], g_sh1[WIDTH];
__device__ float g_sc2[WIDTH], g_sh2[WIDTH];
__device__ float g_sc3[OUTC],  g_sh3[OUTC];

// ---------------- helpers ----------------
__device__ __forceinline__ float red_max16(float v) {
#pragma unroll
    for (int d = 8; d; d >>= 1) v = fmaxf(v, __shfl_xor_sync(0xffffffffu, v, d, 16));
    return v;
}
__device__ __forceinline__ float red_sum16(float v) {
#pragma unroll
    for (int d = 8; d; d >>= 1) v += __shfl_xor_sync(0xffffffffu, v, d, 16);
    return v;
}
__device__ __forceinline__ void softmax_store(float s, float* attn_f, int nl, int kidx) {
    const float m = red_max16(s);
    const float e = __expf(s - m);
    const float sum = red_sum16(e);
    attn_f[nl * 34 + kidx] = e / sum;
}

// GEMM 24x32x256 per iteration (2 codebooks fused).
// attn2: float2 rows stride 17; lut_s: [32 k][256 cols].
__device__ __forceinline__ void gemm2(const float2* attn2, const float* lut_s,
                                      int pn, int po, float acc[6][4]) {
#pragma unroll
    for (int kp = 0; kp < 16; ++kp) {
        const float4 bv0 = ((const float4*)lut_s)[(2 * kp    ) * 64 + po];
        const float4 bv1 = ((const float4*)lut_s)[(2 * kp + 1) * 64 + po];
#pragma unroll
        for (int i = 0; i < 6; ++i) {
            const float2 a = attn2[(pn * 6 + i) * 17 + kp];
            acc[i][0] = fmaf(a.x, bv0.x, acc[i][0]);
            acc[i][1] = fmaf(a.x, bv0.y, acc[i][1]);
            acc[i][2] = fmaf(a.x, bv0.z, acc[i][2]);
            acc[i][3] = fmaf(a.x, bv0.w, acc[i][3]);
            acc[i][0] = fmaf(a.y, bv1.x, acc[i][0]);
            acc[i][1] = fmaf(a.y, bv1.y, acc[i][1]);
            acc[i][2] = fmaf(a.y, bv1.z, acc[i][2]);
            acc[i][3] = fmaf(a.y, bv1.w, acc[i][3]);
        }
    }
}

__device__ __forceinline__ void epi_store(float* dst, int obase, int n0, int TILE,
                                          int pn, int po, const float acc[6][4]) {
#pragma unroll
    for (int i = 0; i < 6; ++i) {
        const int row = pn * 6 + i;
        if (row < TILE) {
            const int n = n0 + row;
#pragma unroll
            for (int q = 0; q < 4; ++q)
                dst[(size_t)(obase + po * 4 + q) * NPOS + n] = acc[i][q];
        }
    }
}

// ======================= AMM layer 1 (1x1, ncb=256, sub=4) =================
__global__ __launch_bounds__(256, 2) void amm1_kernel(
    const float* __restrict__ x, const float* __restrict__ cent,
    const float* __restrict__ lut, const float* __restrict__ invt_p)
{
    __shared__ float lut_s[2 * KC * 256];    // 32 KB (2 codebooks)
    __shared__ float2 attn2_s[ROWS * 17];    // stride 34 floats
    __shared__ float xv_s[8 * ROWS];

    const int t = threadIdx.x, bx = blockIdx.x;
    const int TILE = TB + (bx < 56);
    const int n0 = bx * TB + (bx < 56 ? bx : 56);
    const float invt = __ldg(invt_p);

    const int po = t & 63, pn = t >> 6;
    float acc[6][4];
#pragma unroll
    for (int i = 0; i < 6; ++i)
#pragma unroll
        for (int q = 0; q < 4; ++q) acc[i][q] = 0.f;

    // xv loader: 8 channel-groups x 24 rows
    const int lj = t >> 5, lnl = t & 31;
    const bool ldr = lnl < ROWS;
    const int ln = n0 + min(lnl, TILE - 1);
    const int lb = ln / L_, ll = ln - (ln / L_) * L_;
    const float* xbase = x + (size_t)lb * CIN * L_ + ll + (size_t)lj * L_;

    const int gg = t >> 4, kk = t & 15;
    float* attn_f = (float*)attn2_s;

    for (int it = 0; it < 128; ++it) {
        float4 lr[8];
        const float4* lp = (const float4*)lut + (size_t)it * 2048;
#pragma unroll
        for (int r = 0; r < 8; ++r) lr[r] = __ldg(lp + t + r * 256);

        if (ldr)
            xv_s[lj * ROWS + lnl] = __ldg(xbase + (size_t)(it * 8) * L_);
        __syncthreads();

#pragma unroll
        for (int r = 0; r < 8; ++r) ((float4*)lut_s)[t + r * 256] = lr[r];

        {   // scoring + softmax: 4 passes (2 per codebook)
            const int c2 = it * 2;
            float cw[2][4], nrm[2];
#pragma unroll
            for (int cb = 0; cb < 2; ++cb) {
                const float* cp = cent + ((size_t)(c2 + cb) * KC + kk) * 4;
                cw[cb][0] = __ldg(cp);     cw[cb][1] = __ldg(cp + 1);
                cw[cb][2] = __ldg(cp + 2); cw[cb][3] = __ldg(cp + 3);
                nrm[cb] = cw[cb][0]*cw[cb][0] + cw[cb][1]*cw[cb][1]
                        + cw[cb][2]*cw[cb][2] + cw[cb][3]*cw[cb][3];
            }
#pragma unroll
            for (int p = 0; p < 4; ++p) {
                const int cb = p >> 1, nl = (p & 1) * 16 + gg;
                if (nl < ROWS) {
                    const float* xb = xv_s + cb * 4 * ROWS;
                    float s = cw[cb][0] * xb[nl]            + cw[cb][1] * xb[ROWS + nl]
                            + cw[cb][2] * xb[2 * ROWS + nl] + cw[cb][3] * xb[3 * ROWS + nl];
                    s = (2.f * s - nrm[cb]) * invt;
                    softmax_store(s, attn_f, nl, cb * 16 + kk);
                }
            }
        }
        __syncthreads();

        gemm2(attn2_s, lut_s, pn, po, acc);
        __syncthreads();
    }
    epi_store(g_out1, 0, n0, TILE, pn, po, acc);
}

// ============ AMM layer 2 (3x3 patches, ncb=256, sub=9, bn1+relu fused) ====
__global__ __launch_bounds__(256, 2) void amm2_kernel(
    const float* __restrict__ cent, const float* __restrict__ lut,
    const float* __restrict__ invt_p)
{
    __shared__ float lut_s[2 * KC * 256];
    __shared__ float2 attn2_s[ROWS * 17];
    __shared__ float xv_s[2 * 9 * ROWS];     // 432 entries

    const int t = threadIdx.x, bx = blockIdx.x;
    const int TILE = TB + (bx < 56);
    const int n0 = bx * TB + (bx < 56 ? bx : 56);
    const float invt = __ldg(invt_p);

    const int po = t & 63, pn = t >> 6;
    float acc[6][4];
#pragma unroll
    for (int i = 0; i < 6; ++i)
#pragma unroll
        for (int q = 0; q < 4; ++q) acc[i][q] = 0.f;

    // patch-gather precompute: slot idx = cb*216 + s9*24 + nl, 2 rounds
    int posn[2]; bool vld[2]; int cbr[2];
#pragma unroll
    for (int r = 0; r < 2; ++r) {
        const int idx = t + r * 256;
        vld[r] = false; posn[r] = 0; cbr[r] = 0;
        if (idx < 432) {
            cbr[r] = idx / 216;
            const int rem = idx - cbr[r] * 216;
            const int s9 = rem / ROWS, nl = rem - s9 * ROWS;
            const int n = n0 + min(nl, TILE - 1);
            const int b = n / L_, l = n - (n / L_) * L_;
            const int h = l / W_, w = l - (l / W_) * W_;
            const int hh = h + s9 / 3 - 1, ww = w + s9 % 3 - 1;
            vld[r] = (hh >= 0 && hh < H_ && ww >= 0 && ww < W_);
            posn[r] = b * L_ + (vld[r] ? hh * W_ + ww : 0);
        }
    }

    const int gg = t >> 4, kk = t & 15;
    float* attn_f = (float*)attn2_s;

    for (int it = 0; it < 128; ++it) {
        const int c2 = it * 2;
        float4 lr[8];
        const float4* lp = (const float4*)lut + (size_t)it * 2048;
#pragma unroll
        for (int r = 0; r < 8; ++r) lr[r] = __ldg(lp + t + r * 256);

#pragma unroll
        for (int r = 0; r < 2; ++r) {
            const int idx = t + r * 256;
            if (idx < 432) {
                const int ch = c2 + cbr[r];
                float v = 0.f;
                if (vld[r])
                    v = fmaxf(fmaf(__ldg(g_out1 + (size_t)ch * NPOS + posn[r]),
                                   g_sc1[ch], g_sh1[ch]), 0.f);
                xv_s[idx] = v;
            }
        }
        __syncthreads();

#pragma unroll
        for (int r = 0; r < 8; ++r) ((float4*)lut_s)[t + r * 256] = lr[r];

        {
            float cw[2][9], nrm[2];
#pragma unroll
            for (int cb = 0; cb < 2; ++cb) {
                const float* cp = cent + ((size_t)(c2 + cb) * KC + kk) * 9;
                nrm[cb] = 0.f;
#pragma unroll
                for (int j = 0; j < 9; ++j) {
                    cw[cb][j] = __ldg(cp + j);
                    nrm[cb] = fmaf(cw[cb][j], cw[cb][j], nrm[cb]);
                }
            }
#pragma unroll
            for (int p = 0; p < 4; ++p) {
                const int cb = p >> 1, nl = (p & 1) * 16 + gg;
                if (nl < ROWS) {
                    const float* xb = xv_s + cb * 216;
                    float s = 0.f;
#pragma unroll
                    for (int j = 0; j < 9; ++j) s = fmaf(cw[cb][j], xb[j * ROWS + nl], s);
                    s = (2.f * s - nrm[cb]) * invt;
                    softmax_store(s, attn_f, nl, cb * 16 + kk);
                }
            }
        }
        __syncthreads();

        gemm2(attn2_s, lut_s, pn, po, acc);
        __syncthreads();
    }
    epi_store(g_out2, 0, n0, TILE, pn, po, acc);
}

// ======= AMM layer 3 (1x1, ncb=64, sub=4, out=1024, bn2+relu fused) ========
// grid (296, 4): exactly 8 blocks per SM
__global__ __launch_bounds__(256, 2) void amm3_kernel(
    const float* __restrict__ cent, const float* __restrict__ lut,
    const float* __restrict__ invt_p)
{
    __shared__ float lut_s[2 * KC * 256];
    __shared__ float2 attn2_s[ROWS * 17];
    __shared__ float xv_s[8 * ROWS];

    const int t = threadIdx.x, bx = blockIdx.x;
    const int obase = blockIdx.y << 8;
    const int TILE = TB + (bx < 56);
    const int n0 = bx * TB + (bx < 56 ? bx : 56);
    const float invt = __ldg(invt_p);

    const int po = t & 63, pn = t >> 6;
    float acc[6][4];
#pragma unroll
    for (int i = 0; i < 6; ++i)
#pragma unroll
        for (int q = 0; q < 4; ++q) acc[i][q] = 0.f;

    const int lj = t >> 5, lnl = t & 31;
    const bool ldr = lnl < ROWS;
    const int ln = n0 + min(lnl, TILE - 1);

    const int gg = t >> 4, kk = t & 15;
    float* attn_f = (float*)attn2_s;

    for (int it = 0; it < 32; ++it) {
        float4 lr[8];
#pragma unroll
        for (int r = 0; r < 8; ++r) {
            const int j = t + r * 256, kg = j >> 6, o4 = j & 63;
            lr[r] = __ldg((const float4*)(lut + ((size_t)(it * 32 + kg)) * OUTC + obase) + o4);
        }

        if (ldr) {
            const int ch = it * 8 + lj;
            xv_s[lj * ROWS + lnl] =
                fmaxf(fmaf(g_out2[(size_t)ch * NPOS + ln], g_sc2[ch], g_sh2[ch]), 0.f);
        }
        __syncthreads();

#pragma unroll
        for (int r = 0; r < 8; ++r) ((float4*)lut_s)[t + r * 256] = lr[r];

        {
            const int c2 = it * 2;
            float cw[2][4], nrm[2];
#pragma unroll
            for (int cb = 0; cb < 2; ++cb) {
                const float* cp = cent + ((size_t)(c2 + cb) * KC + kk) * 4;
                cw[cb][0] = __ldg(cp);     cw[cb][1] = __ldg(cp + 1);
                cw[cb][2] = __ldg(cp + 2); cw[cb][3] = __ldg(cp + 3);
                nrm[cb] = cw[cb][0]*cw[cb][0] + cw[cb][1]*cw[cb][1]
                        + cw[cb][2]*cw[cb][2] + cw[cb][3]*cw[cb][3];
            }
#pragma unroll
            for (int p = 0; p < 4; ++p) {
                const int cb = p >> 1, nl = (p & 1) * 16 + gg;
                if (nl < ROWS) {
                    const float* xb = xv_s + cb * 4 * ROWS;
                    float s = cw[cb][0] * xb[nl]            + cw[cb][1] * xb[ROWS + nl]
                            + cw[cb][2] * xb[2 * ROWS + nl] + cw[cb][3] * xb[3 * ROWS + nl];
                    s = (2.f * s - nrm[cb]) * invt;
                    softmax_store(s, attn_f, nl, cb * 16 + kk);
                }
            }
        }
        __syncthreads();

        gemm2(attn2_s, lut_s, pn, po, acc);
        __syncthreads();
    }
    epi_store(g_out3, obase, n0, TILE, pn, po, acc);
}

// ================== BN batch-stats (one block per channel) =================
__global__ __launch_bounds__(256) void bn_stats_kernel(
    int which, const float* __restrict__ gw, const float* __restrict__ bw)
{
    const float* data; float* scale; float* shift;
    if (which == 0)      { data = g_out1; scale = g_sc1; shift = g_sh1; }
    else if (which == 1) { data = g_out2; scale = g_sc2; shift = g_sh2; }
    else                 { data = g_out3; scale = g_sc3; shift = g_sh3; }

    const int c = blockIdx.x, t = threadIdx.x;
    const float* p = data + (size_t)c * NPOS;
    float s = 0.f, s2 = 0.f;
    for (int i = t; i < NPOS; i += 256) {
        const float v = p[i];
        s += v; s2 += v * v;
    }
#pragma unroll
    for (int d = 16; d; d >>= 1) {
        s  += __shfl_xor_sync(0xffffffffu, s,  d);
        s2 += __shfl_xor_sync(0xffffffffu, s2, d);
    }
    __shared__ float sh_s[8], sh_s2[8];
    if ((t & 31) == 0) { sh_s[t >> 5] = s; sh_s2[t >> 5] = s2; }
    __syncthreads();
    if (t == 0) {
        s = 0.f; s2 = 0.f;
#pragma unroll
        for (int i = 0; i < 8; ++i) { s += sh_s[i]; s2 += sh_s2[i]; }
        const float m   = s  * (1.f / NPOS);
        const float var = s2 * (1.f / NPOS) - m * m;
        const float sc  = __ldg(gw + c) * rsqrtf(var + 1e-5f);
        scale[c] = sc;
        shift[c] = __ldg(bw + c) - m * sc;
    }
}

// ============== final: bn3 + residual + relu ===============================
__global__ __launch_bounds__(256) void final_kernel(
    const float* __restrict__ x, float* __restrict__ out)
{
    const int idx = blockIdx.x * 256 + threadIdx.x;
    if (idx >= B_ * OUTC * L_) return;
    const int l = idx % L_;
    const int c = (idx / L_) % OUTC;
    const int b = idx / (L_ * OUTC);
    const int n = b * L_ + l;
    const float v = g_out3[(size_t)c * NPOS + n] * g_sc3[c] + g_sh3[c] + x[idx];
    out[idx] = fmaxf(v, 0.f);
}

// === 1 dummy: shifts the ncu capture slot onto amm1 or amm2 ===
__global__ void dummy_kernel() {}

// ==========================================================================
extern "C" void kernel_launch(void* const* d_in, const int* in_sizes, int n_in,
                              void* d_out, int out_size)
{
    (void)in_sizes; (void)n_in; (void)out_size;
    const float* x    = (const float*)d_in[0];
    const float* c1c  = (const float*)d_in[1];
    const float* c1l  = (const float*)d_in[2];
    const float* c1t  = (const float*)d_in[3];
    const float* c2c  = (const float*)d_in[4];
    const float* c2l  = (const float*)d_in[5];
    const float* c2t  = (const float*)d_in[6];
    const float* c3c  = (const float*)d_in[7];
    const float* c3l  = (const float*)d_in[8];
    const float* c3t  = (const float*)d_in[9];
    const float* bn1g = (const float*)d_in[10];
    const float* bn1b = (const float*)d_in[11];
    const float* bn2g = (const float*)d_in[12];
    const float* bn2b = (const float*)d_in[13];
    const float* bn3g = (const float*)d_in[14];
    const float* bn3b = (const float*)d_in[15];
    float* out = (float*)d_out;

    dummy_kernel<<<1, 32>>>();

    amm1_kernel<<<NBLK, 256>>>(x, c1c, c1l, c1t);
    bn_stats_kernel<<<WIDTH, 256>>>(0, bn1g, bn1b);

    amm2_kernel<<<NBLK, 256>>>(c2c, c2l, c2t);
    bn_stats_kernel<<<WIDTH, 256>>>(1, bn2g, bn2b);

    amm3_kernel<<<dim3(NBLK, 4), 256>>>(c3c, c3l, c3t);
    bn_stats_kernel<<<OUTC, 256>>>(2, bn3g, bn3b);
    final_kernel<<<(B_ * OUTC * L_ + 255) / 256, 256>>>(x, out);
}